// round 13
// baseline (speedup 1.0000x reference)
#include <cuda_runtime.h>

// HOAF: per-group (G=32, cpg=8) polynomial expansion (164 features) +
// per-group 8x164 matvec. B=16, C=256, HW=3136.
//
// R7: R2 (109us) and R6 (115us) both issue-stall-bound per warp: weights are
// LDS'd right before their dependent FMAs. Occupancy +50% (R6) bought only
// +2pts issue -> it's dependency latency, not warp count. Fix: store weights
// in smem in TRAVERSAL order and software-pipeline the weight loads with a
// static-SSA distance-1 prefetch (named ulonglong2 stages, rotated by
// assignment; no dynamic register indexing -- that's what broke R5).
// Body = R2 shape: 2 pixel-units (batches z, z+8) x 8 outputs, TPB 224,
// bounds(224,2). Est regs ~125 (cap 146). Predicted: issue ~57%, fma ~78%,
// ~80us.

typedef unsigned long long u64;

#define HW   3136
#define TPB  224

__device__ __forceinline__ u64 fma2(u64 a, u64 b, u64 c) {
    u64 d;
    asm("fma.rn.f32x2 %0, %1, %2, %3;" : "=l"(d) : "l"(a), "l"(b), "l"(c));
    return d;
}
__device__ __forceinline__ u64 mul2(u64 a, u64 b) {
    u64 d;
    asm("mul.rn.f32x2 %0, %1, %2;" : "=l"(d) : "l"(a), "l"(b));
    return d;
}

__global__ __launch_bounds__(TPB, 2) void hoaf_kernel(
    const float* __restrict__ x,
    const float* __restrict__ w1, const float* __restrict__ b1,
    const float* __restrict__ w2, const float* __restrict__ b2,
    const float* __restrict__ w3, const float* __restrict__ b3,
    float* __restrict__ out)
{
    // Weights in TRAVERSAL order: t=0..7 deg1; then for (i,j) i<=j: the pair
    // feature followed by its triples (i,j,k), k=j..7. 8 outputs per feature,
    // each (w,w)-packed.
    __shared__ alignas(16) u64 wdup[1312];
    __shared__ u64 biasdup[8];

    const int tid = threadIdx.x;
    const int g = blockIdx.y;

    // Stage weights: map traversal index t -> reference tensor element.
    for (int idx = tid; idx < 1312; idx += TPB) {
        const int t = idx >> 3;
        const int o = idx & 7;
        float v;
        if (t < 8) {
            v = w1[(g * 8 + o) * 8 + t];
        } else {
            int tt = t - 8;
            int p2 = 0, p3 = 0, fi = 0, fj = 0, rem = 0;
            bool found = false;
            for (int i = 0; i < 8 && !found; i++) {
                for (int j = i; j < 8; j++) {
                    const int blk = 1 + (8 - j);   // pair + its triples
                    if (tt < blk) { fi = i; fj = j; rem = tt; found = true; break; }
                    tt -= blk; p2++; p3 += 8 - j;
                }
            }
            (void)fi;
            if (rem == 0)
                v = w2[(g * 8 + o) * 36 + p2];          // pair (i,j)
            else
                v = w3[(g * 8 + o) * 120 + p3 + (rem - 1)];  // triple (i,j,j+rem-1)
        }
        const unsigned int u = __float_as_uint(v);
        wdup[idx] = ((u64)u << 32) | u;
    }
    if (tid < 8) {
        const float v = b1[g * 8 + tid] + b2[g * 8 + tid] + b3[g * 8 + tid];
        const unsigned int u = __float_as_uint(v);
        biasdup[tid] = ((u64)u << 32) | u;
    }
    __syncthreads();

    // Pixel pair p in batches z and z+8.
    const int p = (blockIdx.x * TPB + tid) * 2;
    const size_t gbase = ((size_t)blockIdx.z * 256 + (size_t)g * 8) * HW + p;
    const size_t bstr  = (size_t)8 * 256 * HW;

    u64 XA[8], XB[8], accA[8], accB[8];
#pragma unroll
    for (int k = 0; k < 8; k++) {
        XA[k] = *(const u64*)(x + gbase + (size_t)k * HW);
        XB[k] = *(const u64*)(x + gbase + bstr + (size_t)k * HW);
    }
#pragma unroll
    for (int o = 0; o < 8; o++) { accA[o] = biasdup[o]; accB[o] = accA[o]; }

    // Static-SSA distance-1 weight pipeline: cw = weights of current feature,
    // prefetched one full feature block ahead (16 FFMA2 >= 32 issue cycles
    // covers the ~29cyc LDS latency inside a single warp).
    ulonglong2 cw0, cw1, cw2, cw3;
    {
        const ulonglong2* wp = (const ulonglong2*)wdup;
        cw0 = wp[0]; cw1 = wp[1]; cw2 = wp[2]; cw3 = wp[3];
    }

    int fc = 0;   // flat traversal feature index (constant-folds under unroll)

    auto step = [&](u64 fA, u64 fB) {
        ulonglong2 n0, n1, n2, n3;
        const bool more = (fc + 1 < 164);
        if (more) {
            const ulonglong2* wp = (const ulonglong2*)(wdup + (fc + 1) * 8);
            n0 = wp[0]; n1 = wp[1]; n2 = wp[2]; n3 = wp[3];
        }
        accA[0] = fma2(fA, cw0.x, accA[0]);
        accB[0] = fma2(fB, cw0.x, accB[0]);
        accA[1] = fma2(fA, cw0.y, accA[1]);
        accB[1] = fma2(fB, cw0.y, accB[1]);
        accA[2] = fma2(fA, cw1.x, accA[2]);
        accB[2] = fma2(fB, cw1.x, accB[2]);
        accA[3] = fma2(fA, cw1.y, accA[3]);
        accB[3] = fma2(fB, cw1.y, accB[3]);
        accA[4] = fma2(fA, cw2.x, accA[4]);
        accB[4] = fma2(fB, cw2.x, accB[4]);
        accA[5] = fma2(fA, cw2.y, accA[5]);
        accB[5] = fma2(fB, cw2.y, accB[5]);
        accA[6] = fma2(fA, cw3.x, accA[6]);
        accB[6] = fma2(fB, cw3.x, accB[6]);
        accA[7] = fma2(fA, cw3.y, accA[7]);
        accB[7] = fma2(fB, cw3.y, accB[7]);
        if (more) { cw0 = n0; cw1 = n1; cw2 = n2; cw3 = n3; }
        fc++;
    };

    // Degree 1 (traversal t = 0..7)
#pragma unroll
    for (int k = 0; k < 8; k++)
        step(XA[k], XB[k]);

    // Per (i,j): pair feature then its triples (traversal order == smem order)
#pragma unroll
    for (int i = 0; i < 8; i++) {
#pragma unroll
        for (int j = i; j < 8; j++) {
            const u64 pA = mul2(XA[i], XA[j]);
            const u64 pB = mul2(XB[i], XB[j]);
            step(pA, pB);
#pragma unroll
            for (int k = j; k < 8; k++)
                step(mul2(pA, XA[k]), mul2(pB, XB[k]));
        }
    }

#pragma unroll
    for (int o = 0; o < 8; o++) {
        *(u64*)(out + gbase + (size_t)o * HW) = accA[o];
        *(u64*)(out + gbase + bstr + (size_t)o * HW) = accB[o];
    }
}

extern "C" void kernel_launch(void* const* d_in, const int* in_sizes, int n_in,
                              void* d_out, int out_size)
{
    const float* x  = (const float*)d_in[0];
    const float* w1 = (const float*)d_in[1];
    const float* b1 = (const float*)d_in[2];
    const float* w2 = (const float*)d_in[3];
    const float* b2 = (const float*)d_in[4];
    const float* w3 = (const float*)d_in[5];
    const float* b3 = (const float*)d_in[6];

    dim3 grid(7, 32, 8);    // pixel-pair chunks, groups, batch pairs
    dim3 block(TPB);
    hoaf_kernel<<<grid, block>>>(x, w1, b1, w2, b2, w3, b3, (float*)d_out);
}